// round 3
// baseline (speedup 1.0000x reference)
#include <cuda_runtime.h>
#include <math_constants.h>

// Problem constants (fixed by setup_inputs)
#define NB    2
#define LQ_   4096
#define LKV_  2048
#define H_    16
#define DH_   64
#define DM_   1024     // = H_*DH_ = model dim everywhere
#define SPAN_ 16
#define STRIDE_ 2

// Scratch (static device globals; no allocation in kernel_launch)
__device__ float g_Q  [(size_t)NB * LQ_  * DM_];   // projected Q  [B, LQ, H*DH]
__device__ float g_K  [(size_t)NB * LKV_ * DM_];   // projected K
__device__ float g_V  [(size_t)NB * LKV_ * DM_];   // projected V
__device__ float g_ctx[(size_t)NB * LQ_  * DM_];   // attention context
__device__ float g_W  [(size_t)NB * H_ * LKV_ * SPAN_]; // column-softmax weights

// ---------------------------------------------------------------------------
// Classic SMEM-tiled fp32 GEMM: C[M,N] = A[M,K] @ B[K,N], all row-major.
// BM=BN=128, BK=16, 256 threads, 8x8 per-thread microtile.
// Requires M%128==0, N%128==0, K%16==0 (true for all 4 calls here).
// ---------------------------------------------------------------------------
__global__ __launch_bounds__(256, 2)
void sgemm_kernel(const float* __restrict__ A, const float* __restrict__ B,
                  float* __restrict__ C, int M, int N, int K)
{
    const int BM = 128, BN = 128, BK = 16, TM = 8, TN = 8;
    __shared__ float As[BK][BM];
    __shared__ float Bs[BK][BN];

    const int tid  = threadIdx.x;         // 0..255
    const int bm   = blockIdx.y * BM;
    const int bn   = blockIdx.x * BN;
    const int trow = tid / 16;            // 0..15 (M direction)
    const int tcol = tid % 16;            // 0..15 (N direction)

    float acc[TM][TN];
#pragma unroll
    for (int i = 0; i < TM; i++)
#pragma unroll
        for (int j = 0; j < TN; j++) acc[i][j] = 0.f;

    for (int k0 = 0; k0 < K; k0 += BK) {
        // Load A tile (128 rows x 16 cols) -> As transposed [k][m]
#pragma unroll
        for (int l = 0; l < 2; l++) {
            int idx = tid + l * 256;          // 0..511 float4 loads
            int ar  = idx >> 2;               // 0..127
            int ac  = (idx & 3) << 2;         // 0,4,8,12
            float4 v = *(const float4*)(A + (size_t)(bm + ar) * K + k0 + ac);
            As[ac + 0][ar] = v.x;
            As[ac + 1][ar] = v.y;
            As[ac + 2][ar] = v.z;
            As[ac + 3][ar] = v.w;
        }
        // Load B tile (16 rows x 128 cols)
#pragma unroll
        for (int l = 0; l < 2; l++) {
            int idx = tid + l * 256;
            int br  = idx >> 5;                // 0..15
            int bc  = (idx & 31) << 2;         // 0..124
            *(float4*)&Bs[br][bc] =
                *(const float4*)(B + (size_t)(k0 + br) * N + bn + bc);
        }
        __syncthreads();

#pragma unroll
        for (int kk = 0; kk < BK; kk++) {
            float a[TM], bb[TN];
#pragma unroll
            for (int i = 0; i < TM; i++) a[i] = As[kk][trow * TM + i];
#pragma unroll
            for (int j = 0; j < TN; j++) bb[j] = Bs[kk][tcol * TN + j];
#pragma unroll
            for (int i = 0; i < TM; i++)
#pragma unroll
                for (int j = 0; j < TN; j++) acc[i][j] += a[i] * bb[j];
        }
        __syncthreads();
    }

#pragma unroll
    for (int i = 0; i < TM; i++) {
        float* cp = C + (size_t)(bm + trow * TM + i) * N + bn + tcol * TN;
#pragma unroll
        for (int j = 0; j < TN; j += 4) {
            float4 v = make_float4(acc[i][j], acc[i][j + 1], acc[i][j + 2], acc[i][j + 3]);
            *(float4*)(cp + j) = v;
        }
    }
}

// ---------------------------------------------------------------------------
// Pass A: per (b, h, key-column c), compute the SPAN banded scores
//   s[j] = Q[b, 2c+j, h, :] . K[b, c, h, :]   for j in [0, nvalid)
// and softmax over j (this is the reference's softmax over the QUERY axis,
// which for a fixed column touches exactly these rows). One warp per column.
// ---------------------------------------------------------------------------
__global__ __launch_bounds__(256)
void attn_weights_kernel()
{
    const int warps_per_block = 8;
    int gw = blockIdx.x * warps_per_block + (threadIdx.x >> 5);
    if (gw >= NB * H_ * LKV_) return;
    int lane = threadIdx.x & 31;

    int c = gw % LKV_;
    int h = (gw / LKV_) % H_;
    int b = gw / (LKV_ * H_);

    const float* kv = g_K + ((size_t)b * LKV_ + c) * DM_ + h * DH_;
    float k0 = kv[lane * 2 + 0];
    float k1 = kv[lane * 2 + 1];

    int nv = LQ_ - STRIDE_ * c;          // rows available from 2c
    if (nv > SPAN_) nv = SPAN_;          // >= 2 always for these shapes

    const float* qbase = g_Q + ((size_t)b * LQ_ + STRIDE_ * c) * DM_ + h * DH_;

    float s[SPAN_];
#pragma unroll
    for (int j = 0; j < SPAN_; j++) {
        float p = 0.f;
        if (j < nv) {
            const float* qr = qbase + (size_t)j * DM_;
            p = qr[lane * 2] * k0 + qr[lane * 2 + 1] * k1;
        }
#pragma unroll
        for (int o = 16; o > 0; o >>= 1) p += __shfl_xor_sync(0xffffffffu, p, o);
        s[j] = p;   // every lane holds the full dot product
    }

    float m = -CUDART_INF_F;
#pragma unroll
    for (int j = 0; j < SPAN_; j++) if (j < nv && s[j] > m) m = s[j];
    float sum = 0.f;
#pragma unroll
    for (int j = 0; j < SPAN_; j++) {
        if (j < nv) { s[j] = __expf(s[j] - m); sum += s[j]; }
        else s[j] = 0.f;
    }
    float inv = 1.f / sum;
    if (lane < SPAN_)
        g_W[(size_t)gw * SPAN_ + lane] = s[lane] * inv;
}

// ---------------------------------------------------------------------------
// Pass B: per (b, row r), thread = (h, d). Gather <= 8 weighted V rows:
//   ctx[b,r,h,d] = sum over valid c of w[b,h,c, r-2c] * V[b,c,h,d]
// Valid c: max(0, ceil((r-SPAN+1)/2)) <= c <= r/2.
// ---------------------------------------------------------------------------
__global__ __launch_bounds__(1024)
void attn_ctx_kernel()
{
    int r = blockIdx.x % LQ_;
    int b = blockIdx.x / LQ_;
    int h = threadIdx.x >> 6;        // 0..15
    int d = threadIdx.x & 63;        // 0..63

    int c_hi = r >> 1;
    int c_lo = r - (SPAN_ - 1) <= 0 ? 0 : ((r - (SPAN_ - 1) + 1) >> 1); // ceil((r-15)/2)

    const float* vbase = g_V + (size_t)b * LKV_ * DM_ + h * DH_ + d;
    const float* wbase = g_W + (((size_t)b * H_ + h) * LKV_) * SPAN_;

    float acc = 0.f;
#pragma unroll
    for (int i = 0; i < (SPAN_ / STRIDE_); i++) {
        int c = c_hi - i;
        if (c < c_lo) break;
        int j = r - STRIDE_ * c;                 // 0..15
        float w = wbase[(size_t)c * SPAN_ + j];
        acc += w * vbase[(size_t)c * DM_];
    }
    g_ctx[((size_t)b * LQ_ + r) * DM_ + h * DH_ + d] = acc;
}

// ---------------------------------------------------------------------------
extern "C" void kernel_launch(void* const* d_in, const int* in_sizes, int n_in,
                              void* d_out, int out_size)
{
    const float* q  = (const float*)d_in[0];
    const float* k  = (const float*)d_in[1];
    const float* v  = (const float*)d_in[2];
    const float* Wq = (const float*)d_in[3];
    const float* Wk = (const float*)d_in[4];
    const float* Wv = (const float*)d_in[5];
    const float* Wo = (const float*)d_in[6];
    float* out = (float*)d_out;

    float *pQ, *pK, *pV, *pCtx;
    cudaGetSymbolAddress((void**)&pQ,   g_Q);
    cudaGetSymbolAddress((void**)&pK,   g_K);
    cudaGetSymbolAddress((void**)&pV,   g_V);
    cudaGetSymbolAddress((void**)&pCtx, g_ctx);

    // Q projection: [B*LQ, DM] @ [DM, DM]
    {
        dim3 grid(DM_ / 128, (NB * LQ_) / 128);
        sgemm_kernel<<<grid, 256>>>(q, Wq, pQ, NB * LQ_, DM_, DM_);
    }
    // K projection: [B*LKV, DM] @ [DM, DM]
    {
        dim3 grid(DM_ / 128, (NB * LKV_) / 128);
        sgemm_kernel<<<grid, 256>>>(k, Wk, pK, NB * LKV_, DM_, DM_);
    }
    // V projection
    {
        dim3 grid(DM_ / 128, (NB * LKV_) / 128);
        sgemm_kernel<<<grid, 256>>>(v, Wv, pV, NB * LKV_, DM_, DM_);
    }
    // Pass A: column softmax weights (one warp per (b,h,c))
    {
        int total_warps = NB * H_ * LKV_;
        int blocks = (total_warps + 7) / 8;
        attn_weights_kernel<<<blocks, 256>>>();
    }
    // Pass B: gather context
    {
        attn_ctx_kernel<<<NB * LQ_, 1024>>>();
    }
    // Output projection: ctx [B*LQ, DM] @ Wo [DM, DM] -> out
    {
        dim3 grid(DM_ / 128, (NB * LQ_) / 128);
        sgemm_kernel<<<grid, 256>>>(pCtx, Wo, out, NB * LQ_, DM_, DM_);
    }
}

// round 9
// speedup vs baseline: 2.0991x; 2.0991x over previous
#include <cuda_runtime.h>
#include <cuda_bf16.h>
#include <math_constants.h>
#include <cstdint>

// Problem constants (fixed by setup_inputs)
#define NB    2
#define LQ_   4096
#define LKV_  2048
#define H_    16
#define DH_   64
#define DM_   1024     // = H_*DH_ = model dim everywhere
#define SPAN_ 16
#define STRIDE_ 2

// ---------------------------------------------------------------------------
// PTX helpers — base sm_103 target ONLY (no 'a'-suffix features!)
// ---------------------------------------------------------------------------
__device__ __forceinline__ uint32_t smem_to_u32(const void* p) {
    uint32_t a;
    asm("{ .reg .u64 t; cvta.to.shared.u64 t, %1; cvt.u32.u64 %0, t; }" : "=r"(a) : "l"(p));
    return a;
}
__device__ __forceinline__ void cp_async16(uint32_t dst, const void* src) {
    asm volatile("cp.async.cg.shared.global [%0], [%1], 16;" :: "r"(dst), "l"(src) : "memory");
}
#define CP_ASYNC_COMMIT() asm volatile("cp.async.commit_group;" ::: "memory")
#define CP_ASYNC_WAIT1()  asm volatile("cp.async.wait_group 1;" ::: "memory")

__device__ __forceinline__ void ldmatrix_x4(uint32_t* r, uint32_t addr) {
    asm volatile("ldmatrix.sync.aligned.m8n8.x4.shared.b16 {%0,%1,%2,%3}, [%4];"
        : "=r"(r[0]), "=r"(r[1]), "=r"(r[2]), "=r"(r[3]) : "r"(addr));
}
__device__ __forceinline__ void mma_bf16(float* c, const uint32_t* a, const uint32_t* b) {
    asm volatile("mma.sync.aligned.m16n8k16.row.col.f32.bf16.bf16.f32 "
        "{%0,%1,%2,%3}, {%4,%5,%6,%7}, {%8,%9}, {%0,%1,%2,%3};"
        : "+f"(c[0]), "+f"(c[1]), "+f"(c[2]), "+f"(c[3])
        : "r"(a[0]), "r"(a[1]), "r"(a[2]), "r"(a[3]), "r"(b[0]), "r"(b[1]));
}

// ---------------------------------------------------------------------------
// Scratch (static device globals; no allocation in kernel_launch)
// ---------------------------------------------------------------------------
__device__ float g_Q  [(size_t)NB * LQ_  * DM_];
__device__ float g_K  [(size_t)NB * LKV_ * DM_];
__device__ float g_V  [(size_t)NB * LKV_ * DM_];
__device__ float g_ctx[(size_t)NB * LQ_  * DM_];
__device__ float g_W  [(size_t)NB * H_ * LKV_ * SPAN_];

__device__ __nv_bfloat16 g_Ahi[(size_t)NB * LQ_ * DM_];   // activation split [M,K]
__device__ __nv_bfloat16 g_Alo[(size_t)NB * LQ_ * DM_];
__device__ __nv_bfloat16 g_Bhi[(size_t)DM_ * DM_];        // weight split, TRANSPOSED [N,K]
__device__ __nv_bfloat16 g_Blo[(size_t)DM_ * DM_];

// ---------------------------------------------------------------------------
// fp32 -> (bf16 hi, bf16 lo), same layout, vectorized by 4
// ---------------------------------------------------------------------------
__global__ __launch_bounds__(256)
void split_act_kernel(const float* __restrict__ in,
                      __nv_bfloat16* __restrict__ hi, __nv_bfloat16* __restrict__ lo, int n4)
{
    int i = blockIdx.x * blockDim.x + threadIdx.x;
    if (i >= n4) return;
    float4 v = ((const float4*)in)[i];
    __nv_bfloat16 h0 = __float2bfloat16(v.x);
    __nv_bfloat16 h1 = __float2bfloat16(v.y);
    __nv_bfloat16 h2 = __float2bfloat16(v.z);
    __nv_bfloat16 h3 = __float2bfloat16(v.w);
    __nv_bfloat16 l0 = __float2bfloat16(v.x - __bfloat162float(h0));
    __nv_bfloat16 l1 = __float2bfloat16(v.y - __bfloat162float(h1));
    __nv_bfloat16 l2 = __float2bfloat16(v.z - __bfloat162float(h2));
    __nv_bfloat16 l3 = __float2bfloat16(v.w - __bfloat162float(h3));
    __nv_bfloat162* hp = (__nv_bfloat162*)hi;
    __nv_bfloat162* lp = (__nv_bfloat162*)lo;
    hp[2*i]   = __nv_bfloat162(h0, h1);
    hp[2*i+1] = __nv_bfloat162(h2, h3);
    lp[2*i]   = __nv_bfloat162(l0, l1);
    lp[2*i+1] = __nv_bfloat162(l2, l3);
}

// ---------------------------------------------------------------------------
// fp32 W[K=1024, N=1024] -> bf16 hi/lo TRANSPOSED [N, K]
// ---------------------------------------------------------------------------
__global__ __launch_bounds__(256)
void split_wT_kernel(const float* __restrict__ W,
                     __nv_bfloat16* __restrict__ hi, __nv_bfloat16* __restrict__ lo)
{
    __shared__ float tile[32][33];
    int n0 = blockIdx.x * 32;
    int k0 = blockIdx.y * 32;
    int tx = threadIdx.x & 31;
    int ty = threadIdx.x >> 5;          // 0..7
#pragma unroll
    for (int i = 0; i < 32; i += 8)
        tile[ty + i][tx] = W[(size_t)(k0 + ty + i) * DM_ + n0 + tx];
    __syncthreads();
#pragma unroll
    for (int i = 0; i < 32; i += 8) {
        float x = tile[tx][ty + i];     // W[k0+tx][n0+ty+i]
        __nv_bfloat16 h = __float2bfloat16(x);
        __nv_bfloat16 l = __float2bfloat16(x - __bfloat162float(h));
        size_t o = (size_t)(n0 + ty + i) * DM_ + k0 + tx;
        hi[o] = h;
        lo[o] = l;
    }
}

// ---------------------------------------------------------------------------
// bf16x3 HMMA GEMM: C[M,1024] = A[M,1024] @ B[N,K]^T
//  CTA tile 128x128, 8 warps (4x2), warp tile 32x64, BK=32, 3-stage cp.async.
//  SMEM row layout: 128 bytes/row = [hi k-chunks 0..3 | lo k-chunks 0..3],
//  16B chunks XOR-swizzled with (row & 7) -> conflict-free ldmatrix.
// ---------------------------------------------------------------------------
#define BKG 32
#define NSTG 3
#define STAGE_BYTES 32768            // A 16KB + B 16KB
#define GEMM_SMEM (NSTG * STAGE_BYTES + 128)
#define KSTAGES (DM_ / BKG)          // 32

__device__ __forceinline__ void load_stage_async(uint32_t sbase,
    const __nv_bfloat16* __restrict__ Ahi, const __nv_bfloat16* __restrict__ Alo,
    const __nv_bfloat16* __restrict__ Bhi, const __nv_bfloat16* __restrict__ Blo,
    int bm, int bn, int k0, int tid)
{
    // A: 128 rows x 8 chunks (4 hi + 4 lo), 1024 chunks, 4 per thread
#pragma unroll
    for (int i = 0; i < 4; i++) {
        int idx = tid + i * 256;
        int r = idx >> 3, c = idx & 7;
        const __nv_bfloat16* src =
            (c < 4 ? Ahi : Alo) + (size_t)(bm + r) * DM_ + k0 + (c & 3) * 8;
        cp_async16(sbase + r * 128 + ((c ^ (r & 7)) * 16), src);
    }
    // B: identical shape
#pragma unroll
    for (int i = 0; i < 4; i++) {
        int idx = tid + i * 256;
        int r = idx >> 3, c = idx & 7;
        const __nv_bfloat16* src =
            (c < 4 ? Bhi : Blo) + (size_t)(bn + r) * DM_ + k0 + (c & 3) * 8;
        cp_async16(sbase + 16384 + r * 128 + ((c ^ (r & 7)) * 16), src);
    }
}

__global__ __launch_bounds__(256, 1)
void gemm_bf16x3_mma_kernel(const __nv_bfloat16* __restrict__ Ahi,
                            const __nv_bfloat16* __restrict__ Alo,
                            const __nv_bfloat16* __restrict__ Bhi,
                            const __nv_bfloat16* __restrict__ Blo,
                            float* __restrict__ C)
{
    extern __shared__ char dsmem_raw[];
    uint32_t raw32 = smem_to_u32(dsmem_raw);
    uint32_t smem0 = (raw32 + 127u) & ~127u;

    const int tid = threadIdx.x;
    const int wid = tid >> 5;
    const int lane = tid & 31;
    const int warp_m = wid & 3;          // 4 warps in M
    const int warp_n = wid >> 2;         // 2 warps in N
    const int bm = blockIdx.y * 128;
    const int bn = blockIdx.x * 128;

    float acc[2][8][4];
#pragma unroll
    for (int mf = 0; mf < 2; mf++)
#pragma unroll
        for (int nf = 0; nf < 8; nf++)
#pragma unroll
            for (int q = 0; q < 4; q++) acc[mf][nf][q] = 0.f;

    // Prologue: stages 0 and 1 in flight
    load_stage_async(smem0, Ahi, Alo, Bhi, Blo, bm, bn, 0, tid);
    CP_ASYNC_COMMIT();
    load_stage_async(smem0 + STAGE_BYTES, Ahi, Alo, Bhi, Blo, bm, bn, BKG, tid);
    CP_ASYNC_COMMIT();

    // Precomputed ldmatrix row/lane indexing
    const int a_row0 = warp_m * 32 + (lane & 15);
    const int b_row0 = warp_n * 64 + (lane & 15);
    const int khalf = lane >> 4;         // 0 or 1 (which 8-col group)

    for (int s = 0; s < KSTAGES; s++) {
        CP_ASYNC_WAIT1();               // stage s data resident
        __syncthreads();                // everyone done with buffer (s+2)%3 too
        if (s + 2 < KSTAGES) {
            load_stage_async(smem0 + ((s + 2) % NSTG) * STAGE_BYTES,
                             Ahi, Alo, Bhi, Blo, bm, bn, (s + 2) * BKG, tid);
        }
        CP_ASYNC_COMMIT();              // keep group count in lockstep

        uint32_t As = smem0 + (s % NSTG) * STAGE_BYTES;
        uint32_t Bs = As + 16384;

#pragma unroll
        for (int ks = 0; ks < 2; ks++) {
            uint32_t ah[2][4], al[2][4];
#pragma unroll
            for (int mf = 0; mf < 2; mf++) {
                int row = a_row0 + mf * 16;
                int ch = ks * 2 + khalf;             // hi chunk 0..3
                ldmatrix_x4(ah[mf], As + row * 128 + ((ch ^ (row & 7)) * 16));
                int cl = ch + 4;                     // lo chunk 4..7
                ldmatrix_x4(al[mf], As + row * 128 + ((cl ^ (row & 7)) * 16));
            }
            uint32_t bh[8][2], bl[8][2];
#pragma unroll
            for (int ng = 0; ng < 4; ng++) {
                int row = b_row0 + ng * 16;
                int ch = ks * 2 + khalf;
                uint32_t t[4];
                ldmatrix_x4(t, Bs + row * 128 + ((ch ^ (row & 7)) * 16));
                bh[2*ng][0] = t[0]; bh[2*ng][1] = t[2];
                bh[2*ng+1][0] = t[1]; bh[2*ng+1][1] = t[3];
                int cl = ch + 4;
                ldmatrix_x4(t, Bs + row * 128 + ((cl ^ (row & 7)) * 16));
                bl[2*ng][0] = t[0]; bl[2*ng][1] = t[2];
                bl[2*ng+1][0] = t[1]; bl[2*ng+1][1] = t[3];
            }
#pragma unroll
            for (int mf = 0; mf < 2; mf++)
#pragma unroll
                for (int nf = 0; nf < 8; nf++) {
                    mma_bf16(acc[mf][nf], ah[mf], bh[nf]);
                    mma_bf16(acc[mf][nf], ah[mf], bl[nf]);
                    mma_bf16(acc[mf][nf], al[mf], bh[nf]);
                }
        }
        __syncthreads();
    }

    // Epilogue: write fp32 C
#pragma unroll
    for (int mf = 0; mf < 2; mf++) {
        int row = bm + warp_m * 32 + mf * 16 + (lane >> 2);
#pragma unroll
        for (int nf = 0; nf < 8; nf++) {
            int col = bn + warp_n * 64 + nf * 8 + (lane & 3) * 2;
            *(float2*)(C + (size_t)row * DM_ + col) =
                make_float2(acc[mf][nf][0], acc[mf][nf][1]);
            *(float2*)(C + (size_t)(row + 8) * DM_ + col) =
                make_float2(acc[mf][nf][2], acc[mf][nf][3]);
        }
    }
}

// ---------------------------------------------------------------------------
// Pass A: per (b, h, key-column c): banded scores + softmax over query axis
// ---------------------------------------------------------------------------
__global__ __launch_bounds__(256)
void attn_weights_kernel()
{
    const int warps_per_block = 8;
    int gw = blockIdx.x * warps_per_block + (threadIdx.x >> 5);
    if (gw >= NB * H_ * LKV_) return;
    int lane = threadIdx.x & 31;

    int c = gw % LKV_;
    int h = (gw / LKV_) % H_;
    int b = gw / (LKV_ * H_);

    const float* kv = g_K + ((size_t)b * LKV_ + c) * DM_ + h * DH_;
    float k0 = kv[lane * 2 + 0];
    float k1 = kv[lane * 2 + 1];

    int nv = LQ_ - STRIDE_ * c;
    if (nv > SPAN_) nv = SPAN_;

    const float* qbase = g_Q + ((size_t)b * LQ_ + STRIDE_ * c) * DM_ + h * DH_;

    float s[SPAN_];
#pragma unroll
    for (int j = 0; j < SPAN_; j++) {
        float p = 0.f;
        if (j < nv) {
            const float* qr = qbase + (size_t)j * DM_;
            p = qr[lane * 2] * k0 + qr[lane * 2 + 1] * k1;
        }
#pragma unroll
        for (int o = 16; o > 0; o >>= 1) p += __shfl_xor_sync(0xffffffffu, p, o);
        s[j] = p;
    }

    float m = -CUDART_INF_F;
#pragma unroll
    for (int j = 0; j < SPAN_; j++) if (j < nv && s[j] > m) m = s[j];
    float sum = 0.f;
#pragma unroll
    for (int j = 0; j < SPAN_; j++) {
        if (j < nv) { s[j] = __expf(s[j] - m); sum += s[j]; }
        else s[j] = 0.f;
    }
    float inv = 1.f / sum;
    if (lane < SPAN_)
        g_W[(size_t)gw * SPAN_ + lane] = s[lane] * inv;
}

// ---------------------------------------------------------------------------
// Pass B: gather context rows
// ---------------------------------------------------------------------------
__global__ __launch_bounds__(1024)
void attn_ctx_kernel()
{
    int r = blockIdx.x % LQ_;
    int b = blockIdx.x / LQ_;
    int h = threadIdx.x >> 6;
    int d = threadIdx.x & 63;

    int c_hi = r >> 1;
    int c_lo = r - (SPAN_ - 1) <= 0 ? 0 : ((r - (SPAN_ - 1) + 1) >> 1);

    const float* vbase = g_V + (size_t)b * LKV_ * DM_ + h * DH_ + d;
    const float* wbase = g_W + (((size_t)b * H_ + h) * LKV_) * SPAN_;

    float acc = 0.f;
#pragma unroll
    for (int i = 0; i < (SPAN_ / STRIDE_); i++) {
        int c = c_hi - i;
        if (c < c_lo) break;
        int j = r - STRIDE_ * c;
        float w = wbase[(size_t)c * SPAN_ + j];
        acc += w * vbase[(size_t)c * DM_];
    }
    g_ctx[((size_t)b * LQ_ + r) * DM_ + h * DH_ + d] = acc;
}

// ---------------------------------------------------------------------------
extern "C" void kernel_launch(void* const* d_in, const int* in_sizes, int n_in,
                              void* d_out, int out_size)
{
    const float* q  = (const float*)d_in[0];
    const float* k  = (const float*)d_in[1];
    const float* v  = (const float*)d_in[2];
    const float* Wq = (const float*)d_in[3];
    const float* Wk = (const float*)d_in[4];
    const float* Wv = (const float*)d_in[5];
    const float* Wo = (const float*)d_in[6];
    float* out = (float*)d_out;

    float *pQ, *pK, *pV, *pCtx;
    __nv_bfloat16 *pAhi, *pAlo, *pBhi, *pBlo;
    cudaGetSymbolAddress((void**)&pQ,   g_Q);
    cudaGetSymbolAddress((void**)&pK,   g_K);
    cudaGetSymbolAddress((void**)&pV,   g_V);
    cudaGetSymbolAddress((void**)&pCtx, g_ctx);
    cudaGetSymbolAddress((void**)&pAhi, g_Ahi);
    cudaGetSymbolAddress((void**)&pAlo, g_Alo);
    cudaGetSymbolAddress((void**)&pBhi, g_Bhi);
    cudaGetSymbolAddress((void**)&pBlo, g_Blo);

    cudaFuncSetAttribute(gemm_bf16x3_mma_kernel,
                         cudaFuncAttributeMaxDynamicSharedMemorySize, GEMM_SMEM);

    dim3 wt_grid(32, 32);

    // ---- Q projection: [8192,1024] @ Wq
    split_wT_kernel<<<wt_grid, 256>>>(Wq, pBhi, pBlo);
    {
        int n4 = NB * LQ_ * DM_ / 4;
        split_act_kernel<<<n4 / 256, 256>>>(q, pAhi, pAlo, n4);
        dim3 grid(DM_ / 128, (NB * LQ_) / 128);
        gemm_bf16x3_mma_kernel<<<grid, 256, GEMM_SMEM>>>(pAhi, pAlo, pBhi, pBlo, pQ);
    }
    // ---- K projection: [4096,1024] @ Wk
    split_wT_kernel<<<wt_grid, 256>>>(Wk, pBhi, pBlo);
    {
        int n4 = NB * LKV_ * DM_ / 4;
        split_act_kernel<<<n4 / 256, 256>>>(k, pAhi, pAlo, n4);
        dim3 grid(DM_ / 128, (NB * LKV_) / 128);
        gemm_bf16x3_mma_kernel<<<grid, 256, GEMM_SMEM>>>(pAhi, pAlo, pBhi, pBlo, pK);
    }
    // ---- V projection
    split_wT_kernel<<<wt_grid, 256>>>(Wv, pBhi, pBlo);
    {
        int n4 = NB * LKV_ * DM_ / 4;
        split_act_kernel<<<n4 / 256, 256>>>(v, pAhi, pAlo, n4);
        dim3 grid(DM_ / 128, (NB * LKV_) / 128);
        gemm_bf16x3_mma_kernel<<<grid, 256, GEMM_SMEM>>>(pAhi, pAlo, pBhi, pBlo, pV);
    }
    // ---- Attention
    {
        int total_warps = NB * H_ * LKV_;
        attn_weights_kernel<<<(total_warps + 7) / 8, 256>>>();
        attn_ctx_kernel<<<NB * LQ_, 1024>>>();
    }
    // ---- Output projection: ctx @ Wo -> out
    split_wT_kernel<<<wt_grid, 256>>>(Wo, pBhi, pBlo);
    {
        int n4 = NB * LQ_ * DM_ / 4;
        split_act_kernel<<<n4 / 256, 256>>>(pCtx, pAhi, pAlo, n4);
        dim3 grid(DM_ / 128, (NB * LQ_) / 128);
        gemm_bf16x3_mma_kernel<<<grid, 256, GEMM_SMEM>>>(pAhi, pAlo, pBhi, pBlo, out);
    }
}

// round 10
// speedup vs baseline: 2.1685x; 1.0331x over previous
#include <cuda_runtime.h>
#include <cuda_bf16.h>
#include <math_constants.h>
#include <cstdint>

// Problem constants (fixed by setup_inputs)
#define NB    2
#define LQ_   4096
#define LKV_  2048
#define H_    16
#define DH_   64
#define DM_   1024     // = H_*DH_ = model dim everywhere
#define SPAN_ 16
#define STRIDE_ 2

// ---------------------------------------------------------------------------
// PTX helpers — base sm_103 target ONLY (no 'a'-suffix features!)
// ---------------------------------------------------------------------------
__device__ __forceinline__ uint32_t smem_to_u32(const void* p) {
    uint32_t a;
    asm("{ .reg .u64 t; cvta.to.shared.u64 t, %1; cvt.u32.u64 %0, t; }" : "=r"(a) : "l"(p));
    return a;
}
__device__ __forceinline__ void cp_async16(uint32_t dst, const void* src) {
    asm volatile("cp.async.cg.shared.global [%0], [%1], 16;" :: "r"(dst), "l"(src) : "memory");
}
#define CP_ASYNC_COMMIT() asm volatile("cp.async.commit_group;" ::: "memory")
#define CP_ASYNC_WAIT1()  asm volatile("cp.async.wait_group 1;" ::: "memory")

__device__ __forceinline__ void ldmatrix_x4(uint32_t* r, uint32_t addr) {
    asm volatile("ldmatrix.sync.aligned.m8n8.x4.shared.b16 {%0,%1,%2,%3}, [%4];"
        : "=r"(r[0]), "=r"(r[1]), "=r"(r[2]), "=r"(r[3]) : "r"(addr));
}
__device__ __forceinline__ void mma_bf16(float* c, const uint32_t* a, const uint32_t* b) {
    asm volatile("mma.sync.aligned.m16n8k16.row.col.f32.bf16.bf16.f32 "
        "{%0,%1,%2,%3}, {%4,%5,%6,%7}, {%8,%9}, {%0,%1,%2,%3};"
        : "+f"(c[0]), "+f"(c[1]), "+f"(c[2]), "+f"(c[3])
        : "r"(a[0]), "r"(a[1]), "r"(a[2]), "r"(a[3]), "r"(b[0]), "r"(b[1]));
}

// ---------------------------------------------------------------------------
// Scratch (static device globals; no allocation in kernel_launch)
// ---------------------------------------------------------------------------
__device__ float g_Q  [(size_t)NB * LQ_  * DM_];
__device__ float g_K  [(size_t)NB * LKV_ * DM_];
__device__ float g_V  [(size_t)NB * LKV_ * DM_];
__device__ float g_W  [(size_t)NB * H_ * LKV_ * SPAN_];

__device__ __nv_bfloat16 g_Ahi[(size_t)NB * LQ_ * DM_];   // activation split [M,K]
__device__ __nv_bfloat16 g_Alo[(size_t)NB * LQ_ * DM_];
__device__ __nv_bfloat16 g_Bhi[(size_t)4 * DM_ * DM_];    // 4 weights, TRANSPOSED [N,K]
__device__ __nv_bfloat16 g_Blo[(size_t)4 * DM_ * DM_];

// ---------------------------------------------------------------------------
// fp32 -> (bf16 hi, bf16 lo), same layout, vectorized by 4
// ---------------------------------------------------------------------------
__global__ __launch_bounds__(256)
void split_act_kernel(const float* __restrict__ in,
                      __nv_bfloat16* __restrict__ hi, __nv_bfloat16* __restrict__ lo, int n4)
{
    int i = blockIdx.x * blockDim.x + threadIdx.x;
    if (i >= n4) return;
    float4 v = ((const float4*)in)[i];
    __nv_bfloat16 h0 = __float2bfloat16(v.x);
    __nv_bfloat16 h1 = __float2bfloat16(v.y);
    __nv_bfloat16 h2 = __float2bfloat16(v.z);
    __nv_bfloat16 h3 = __float2bfloat16(v.w);
    __nv_bfloat16 l0 = __float2bfloat16(v.x - __bfloat162float(h0));
    __nv_bfloat16 l1 = __float2bfloat16(v.y - __bfloat162float(h1));
    __nv_bfloat16 l2 = __float2bfloat16(v.z - __bfloat162float(h2));
    __nv_bfloat16 l3 = __float2bfloat16(v.w - __bfloat162float(h3));
    __nv_bfloat162* hp = (__nv_bfloat162*)hi;
    __nv_bfloat162* lp = (__nv_bfloat162*)lo;
    hp[2*i]   = __nv_bfloat162(h0, h1);
    hp[2*i+1] = __nv_bfloat162(h2, h3);
    lp[2*i]   = __nv_bfloat162(l0, l1);
    lp[2*i+1] = __nv_bfloat162(l2, l3);
}

// ---------------------------------------------------------------------------
// All 4 weights: fp32 W[K,N] -> bf16 hi/lo TRANSPOSED [N,K], one launch (z=4)
// ---------------------------------------------------------------------------
__global__ __launch_bounds__(256)
void split_w4_kernel(const float* __restrict__ W0, const float* __restrict__ W1,
                     const float* __restrict__ W2, const float* __restrict__ W3,
                     __nv_bfloat16* __restrict__ hi, __nv_bfloat16* __restrict__ lo)
{
    const float* W = (blockIdx.z == 0) ? W0 : (blockIdx.z == 1) ? W1
                   : (blockIdx.z == 2) ? W2 : W3;
    size_t dst_off = (size_t)blockIdx.z * DM_ * DM_;

    __shared__ float tile[32][33];
    int n0 = blockIdx.x * 32;
    int k0 = blockIdx.y * 32;
    int tx = threadIdx.x & 31;
    int ty = threadIdx.x >> 5;          // 0..7
#pragma unroll
    for (int i = 0; i < 32; i += 8)
        tile[ty + i][tx] = W[(size_t)(k0 + ty + i) * DM_ + n0 + tx];
    __syncthreads();
#pragma unroll
    for (int i = 0; i < 32; i += 8) {
        float x = tile[tx][ty + i];     // W[k0+tx][n0+ty+i]
        __nv_bfloat16 h = __float2bfloat16(x);
        __nv_bfloat16 l = __float2bfloat16(x - __bfloat162float(h));
        size_t o = dst_off + (size_t)(n0 + ty + i) * DM_ + k0 + tx;
        hi[o] = h;
        lo[o] = l;
    }
}

// ---------------------------------------------------------------------------
// bf16x3 HMMA GEMM: C[M,1024] = A[M,1024] @ B[N,K]^T
//  CTA tile 128x128, 8 warps (4x2), warp tile 32x64, BK=32, 3-stage cp.async.
//  2 CTAs/SM. SMEM row: 128B = [hi chunks 0..3 | lo chunks 0..3], XOR-8 swizzle.
// ---------------------------------------------------------------------------
#define BKG 32
#define NSTG 3
#define STAGE_BYTES 32768            // A 16KB + B 16KB
#define GEMM_SMEM (NSTG * STAGE_BYTES + 128)
#define KSTAGES (DM_ / BKG)          // 32

__device__ __forceinline__ void load_stage_async(uint32_t sbase,
    const __nv_bfloat16* __restrict__ Ahi, const __nv_bfloat16* __restrict__ Alo,
    const __nv_bfloat16* __restrict__ Bhi, const __nv_bfloat16* __restrict__ Blo,
    int bm, int bn, int k0, int tid)
{
#pragma unroll
    for (int i = 0; i < 4; i++) {
        int idx = tid + i * 256;
        int r = idx >> 3, c = idx & 7;
        const __nv_bfloat16* src =
            (c < 4 ? Ahi : Alo) + (size_t)(bm + r) * DM_ + k0 + (c & 3) * 8;
        cp_async16(sbase + r * 128 + ((c ^ (r & 7)) * 16), src);
    }
#pragma unroll
    for (int i = 0; i < 4; i++) {
        int idx = tid + i * 256;
        int r = idx >> 3, c = idx & 7;
        const __nv_bfloat16* src =
            (c < 4 ? Bhi : Blo) + (size_t)(bn + r) * DM_ + k0 + (c & 3) * 8;
        cp_async16(sbase + 16384 + r * 128 + ((c ^ (r & 7)) * 16), src);
    }
}

__global__ __launch_bounds__(256, 2)
void gemm_bf16x3_mma_kernel(const __nv_bfloat16* __restrict__ Ahi,
                            const __nv_bfloat16* __restrict__ Alo,
                            const __nv_bfloat16* __restrict__ Bhi,
                            const __nv_bfloat16* __restrict__ Blo,
                            float* __restrict__ C)
{
    extern __shared__ char dsmem_raw[];
    uint32_t raw32 = smem_to_u32(dsmem_raw);
    uint32_t smem0 = (raw32 + 127u) & ~127u;

    const int tid = threadIdx.x;
    const int wid = tid >> 5;
    const int lane = tid & 31;
    const int warp_m = wid & 3;          // 4 warps in M
    const int warp_n = wid >> 2;         // 2 warps in N
    const int bm = blockIdx.y * 128;
    const int bn = blockIdx.x * 128;

    float acc[2][8][4];
#pragma unroll
    for (int mf = 0; mf < 2; mf++)
#pragma unroll
        for (int nf = 0; nf < 8; nf++)
#pragma unroll
            for (int q = 0; q < 4; q++) acc[mf][nf][q] = 0.f;

    // Prologue: stages 0 and 1 in flight
    load_stage_async(smem0, Ahi, Alo, Bhi, Blo, bm, bn, 0, tid);
    CP_ASYNC_COMMIT();
    load_stage_async(smem0 + STAGE_BYTES, Ahi, Alo, Bhi, Blo, bm, bn, BKG, tid);
    CP_ASYNC_COMMIT();

    const int a_row0 = warp_m * 32 + (lane & 15);
    const int b_row0 = warp_n * 64 + (lane & 15);
    const int khalf = lane >> 4;         // 0 or 1

    for (int s = 0; s < KSTAGES; s++) {
        CP_ASYNC_WAIT1();               // stage s resident
        __syncthreads();                // also: everyone finished iter s-1 reads
        if (s + 2 < KSTAGES) {
            load_stage_async(smem0 + ((s + 2) % NSTG) * STAGE_BYTES,
                             Ahi, Alo, Bhi, Blo, bm, bn, (s + 2) * BKG, tid);
        }
        CP_ASYNC_COMMIT();              // keep group count in lockstep

        uint32_t As = smem0 + (s % NSTG) * STAGE_BYTES;
        uint32_t Bs = As + 16384;

#pragma unroll
        for (int ks = 0; ks < 2; ks++) {
            uint32_t ah[2][4], al[2][4];
            const int ch = ks * 2 + khalf;           // hi chunk 0..3
#pragma unroll
            for (int mf = 0; mf < 2; mf++) {
                int row = a_row0 + mf * 16;
                ldmatrix_x4(ah[mf], As + row * 128 + ((ch ^ (row & 7)) * 16));
                ldmatrix_x4(al[mf], As + row * 128 + (((ch + 4) ^ (row & 7)) * 16));
            }
            // Process nf in two groups of 4 to bound live registers (occ 2)
#pragma unroll
            for (int g = 0; g < 2; g++) {
                uint32_t bh[4][2], bl[4][2];
#pragma unroll
                for (int ng = 0; ng < 2; ng++) {
                    int row = b_row0 + (g * 2 + ng) * 16;
                    uint32_t t[4];
                    ldmatrix_x4(t, Bs + row * 128 + ((ch ^ (row & 7)) * 16));
                    bh[2*ng][0] = t[0]; bh[2*ng][1] = t[2];
                    bh[2*ng+1][0] = t[1]; bh[2*ng+1][1] = t[3];
                    ldmatrix_x4(t, Bs + row * 128 + (((ch + 4) ^ (row & 7)) * 16));
                    bl[2*ng][0] = t[0]; bl[2*ng][1] = t[2];
                    bl[2*ng+1][0] = t[1]; bl[2*ng+1][1] = t[3];
                }
#pragma unroll
                for (int mf = 0; mf < 2; mf++)
#pragma unroll
                    for (int nf = 0; nf < 4; nf++) {
                        float* a = acc[mf][g * 4 + nf];
                        mma_bf16(a, ah[mf], bh[nf]);
                        mma_bf16(a, ah[mf], bl[nf]);
                        mma_bf16(a, al[mf], bh[nf]);
                    }
            }
        }
        // no trailing barrier: next iteration's leading sync covers the hazard
    }

    // Epilogue: write fp32 C
#pragma unroll
    for (int mf = 0; mf < 2; mf++) {
        int row = bm + warp_m * 32 + mf * 16 + (lane >> 2);
#pragma unroll
        for (int nf = 0; nf < 8; nf++) {
            int col = bn + warp_n * 64 + nf * 8 + (lane & 3) * 2;
            *(float2*)(C + (size_t)row * DM_ + col) =
                make_float2(acc[mf][nf][0], acc[mf][nf][1]);
            *(float2*)(C + (size_t)(row + 8) * DM_ + col) =
                make_float2(acc[mf][nf][2], acc[mf][nf][3]);
        }
    }
}

// ---------------------------------------------------------------------------
// Pass A (v2): warp per (b,h,c); lane = j*2+half. Each lane computes half of
// the 64-dim dot for band row j; 1 shuffle to combine halves; softmax over j
// via 4 xor-shuffles (offsets 2..16 stay within same-half group of 16 lanes).
// ---------------------------------------------------------------------------
__global__ __launch_bounds__(256)
void attn_weights_kernel()
{
    int gw = blockIdx.x * 8 + (threadIdx.x >> 5);
    if (gw >= NB * H_ * LKV_) return;
    int lane = threadIdx.x & 31;

    int c = gw % LKV_;
    int h = (gw / LKV_) % H_;
    int b = gw / (LKV_ * H_);

    int j    = lane >> 1;       // 0..15 band row
    int half = lane & 1;        // which 32-dim half

    int nv = LQ_ - STRIDE_ * c;
    if (nv > SPAN_) nv = SPAN_;

    const float4* kp = (const float4*)(g_K + ((size_t)b * LKV_ + c) * DM_
                                       + h * DH_ + half * 32);
    float4 k4[8];
#pragma unroll
    for (int i = 0; i < 8; i++) k4[i] = kp[i];

    float d = 0.f;
    if (j < nv) {
        const float4* qp = (const float4*)(g_Q + ((size_t)b * LQ_ + STRIDE_ * c + j) * DM_
                                           + h * DH_ + half * 32);
#pragma unroll
        for (int i = 0; i < 8; i++) {
            float4 qv = qp[i];
            d += qv.x * k4[i].x + qv.y * k4[i].y + qv.z * k4[i].z + qv.w * k4[i].w;
        }
    }
    d += __shfl_xor_sync(0xffffffffu, d, 1);      // combine halves

    float dv = (j < nv) ? d : -CUDART_INF_F;
    float m = dv;
#pragma unroll
    for (int o = 2; o <= 16; o <<= 1) m = fmaxf(m, __shfl_xor_sync(0xffffffffu, m, o));
    float e = (j < nv) ? __expf(dv - m) : 0.f;
    float ssum = e;
#pragma unroll
    for (int o = 2; o <= 16; o <<= 1) ssum += __shfl_xor_sync(0xffffffffu, ssum, o);

    if (half == 0)
        g_W[(size_t)gw * SPAN_ + j] = e / ssum;
}

// ---------------------------------------------------------------------------
// Pass B: gather context rows; FUSED bf16 hi/lo split output (feeds Wo GEMM)
// ---------------------------------------------------------------------------
__global__ __launch_bounds__(1024)
void attn_ctx_kernel(__nv_bfloat16* __restrict__ chi, __nv_bfloat16* __restrict__ clo)
{
    int r = blockIdx.x % LQ_;
    int b = blockIdx.x / LQ_;
    int h = threadIdx.x >> 6;
    int d = threadIdx.x & 63;

    int c_hi = r >> 1;
    int c_lo = r - (SPAN_ - 1) <= 0 ? 0 : ((r - (SPAN_ - 1) + 1) >> 1);

    const float* vbase = g_V + (size_t)b * LKV_ * DM_ + h * DH_ + d;
    const float* wbase = g_W + (((size_t)b * H_ + h) * LKV_) * SPAN_;

    float acc = 0.f;
#pragma unroll
    for (int i = 0; i < (SPAN_ / STRIDE_); i++) {
        int c = c_hi - i;
        if (c < c_lo) break;
        int j = r - STRIDE_ * c;
        float w = wbase[(size_t)c * SPAN_ + j];
        acc += w * vbase[(size_t)c * DM_];
    }
    size_t o = ((size_t)b * LQ_ + r) * DM_ + h * DH_ + d;
    __nv_bfloat16 hi = __float2bfloat16(acc);
    __nv_bfloat16 lo = __float2bfloat16(acc - __bfloat162float(hi));
    chi[o] = hi;
    clo[o] = lo;
}

// ---------------------------------------------------------------------------
extern "C" void kernel_launch(void* const* d_in, const int* in_sizes, int n_in,
                              void* d_out, int out_size)
{
    const float* q  = (const float*)d_in[0];
    const float* k  = (const float*)d_in[1];
    const float* v  = (const float*)d_in[2];
    const float* Wq = (const float*)d_in[3];
    const float* Wk = (const float*)d_in[4];
    const float* Wv = (const float*)d_in[5];
    const float* Wo = (const float*)d_in[6];
    float* out = (float*)d_out;

    float *pQ, *pK, *pV;
    __nv_bfloat16 *pAhi, *pAlo, *pBhi, *pBlo;
    cudaGetSymbolAddress((void**)&pQ,   g_Q);
    cudaGetSymbolAddress((void**)&pK,   g_K);
    cudaGetSymbolAddress((void**)&pV,   g_V);
    cudaGetSymbolAddress((void**)&pAhi, g_Ahi);
    cudaGetSymbolAddress((void**)&pAlo, g_Alo);
    cudaGetSymbolAddress((void**)&pBhi, g_Bhi);
    cudaGetSymbolAddress((void**)&pBlo, g_Blo);

    cudaFuncSetAttribute(gemm_bf16x3_mma_kernel,
                         cudaFuncAttributeMaxDynamicSharedMemorySize, GEMM_SMEM);

    const size_t WSZ = (size_t)DM_ * DM_;

    // ---- All 4 weight splits in one launch (order: Wq, Wk, Wv, Wo)
    {
        dim3 grid(32, 32, 4);
        split_w4_kernel<<<grid, 256>>>(Wq, Wk, Wv, Wo, pBhi, pBlo);
    }
    // ---- Q projection: [8192,1024] @ Wq
    {
        int n4 = NB * LQ_ * DM_ / 4;
        split_act_kernel<<<n4 / 256, 256>>>(q, pAhi, pAlo, n4);
        dim3 grid(DM_ / 128, (NB * LQ_) / 128);
        gemm_bf16x3_mma_kernel<<<grid, 256, GEMM_SMEM>>>(pAhi, pAlo,
                                                         pBhi + 0 * WSZ, pBlo + 0 * WSZ, pQ);
    }
    // ---- K projection: [4096,1024] @ Wk
    {
        int n4 = NB * LKV_ * DM_ / 4;
        split_act_kernel<<<n4 / 256, 256>>>(k, pAhi, pAlo, n4);
        dim3 grid(DM_ / 128, (NB * LKV_) / 128);
        gemm_bf16x3_mma_kernel<<<grid, 256, GEMM_SMEM>>>(pAhi, pAlo,
                                                         pBhi + 1 * WSZ, pBlo + 1 * WSZ, pK);
    }
    // ---- V projection
    {
        int n4 = NB * LKV_ * DM_ / 4;
        split_act_kernel<<<n4 / 256, 256>>>(v, pAhi, pAlo, n4);
        dim3 grid(DM_ / 128, (NB * LKV_) / 128);
        gemm_bf16x3_mma_kernel<<<grid, 256, GEMM_SMEM>>>(pAhi, pAlo,
                                                         pBhi + 2 * WSZ, pBlo + 2 * WSZ, pV);
    }
    // ---- Attention (ctx kernel writes bf16 hi/lo directly into GEMM A bufs)
    {
        int total_warps = NB * H_ * LKV_;
        attn_weights_kernel<<<(total_warps + 7) / 8, 256>>>();
        attn_ctx_kernel<<<NB * LQ_, 1024>>>(pAhi, pAlo);
    }
    // ---- Output projection: ctx @ Wo -> out
    {
        dim3 grid(DM_ / 128, (NB * LQ_) / 128);
        gemm_bf16x3_mma_kernel<<<grid, 256, GEMM_SMEM>>>(pAhi, pAlo,
                                                         pBhi + 3 * WSZ, pBlo + 3 * WSZ, out);
    }
}

// round 14
// speedup vs baseline: 2.1709x; 1.0011x over previous
#include <cuda_runtime.h>
#include <cuda_bf16.h>
#include <math_constants.h>
#include <cstdint>

// Problem constants (fixed by setup_inputs)
#define NB    2
#define LQ_   4096
#define LKV_  2048
#define H_    16
#define DH_   64
#define DM_   1024     // = H_*DH_ = model dim everywhere
#define SPAN_ 16
#define STRIDE_ 2

// ---------------------------------------------------------------------------
// PTX helpers — base sm_103 target ONLY (no 'a'-suffix features!)
// ---------------------------------------------------------------------------
__device__ __forceinline__ uint32_t smem_to_u32(const void* p) {
    uint32_t a;
    asm("{ .reg .u64 t; cvta.to.shared.u64 t, %1; cvt.u32.u64 %0, t; }" : "=r"(a) : "l"(p));
    return a;
}
__device__ __forceinline__ void cp_async16(uint32_t dst, const void* src) {
    asm volatile("cp.async.cg.shared.global [%0], [%1], 16;" :: "r"(dst), "l"(src) : "memory");
}
#define CP_ASYNC_COMMIT() asm volatile("cp.async.commit_group;" ::: "memory")
#define CP_ASYNC_WAIT1()  asm volatile("cp.async.wait_group 1;" ::: "memory")

__device__ __forceinline__ void ldmatrix_x4(uint32_t* r, uint32_t addr) {
    asm volatile("ldmatrix.sync.aligned.m8n8.x4.shared.b16 {%0,%1,%2,%3}, [%4];"
        : "=r"(r[0]), "=r"(r[1]), "=r"(r[2]), "=r"(r[3]) : "r"(addr));
}
__device__ __forceinline__ void mma_bf16(float* c, const uint32_t* a, const uint32_t* b) {
    asm volatile("mma.sync.aligned.m16n8k16.row.col.f32.bf16.bf16.f32 "
        "{%0,%1,%2,%3}, {%4,%5,%6,%7}, {%8,%9}, {%0,%1,%2,%3};"
        : "+f"(c[0]), "+f"(c[1]), "+f"(c[2]), "+f"(c[3])
        : "r"(a[0]), "r"(a[1]), "r"(a[2]), "r"(a[3]), "r"(b[0]), "r"(b[1]));
}

// ---------------------------------------------------------------------------
// Scratch (static device globals; no allocation in kernel_launch)
// ---------------------------------------------------------------------------
__device__ float g_Q  [(size_t)NB * LQ_  * DM_];
__device__ float g_K  [(size_t)NB * LKV_ * DM_];
__device__ float g_V  [(size_t)NB * LKV_ * DM_];
__device__ float g_W  [(size_t)NB * H_ * LKV_ * SPAN_];

__device__ __nv_bfloat16 g_Ahi[(size_t)NB * LQ_ * DM_];   // activation split [M,K]
__device__ __nv_bfloat16 g_Alo[(size_t)NB * LQ_ * DM_];
__device__ __nv_bfloat16 g_Bhi[(size_t)4 * DM_ * DM_];    // 4 weights, TRANSPOSED [N,K]
__device__ __nv_bfloat16 g_Blo[(size_t)4 * DM_ * DM_];

// ---------------------------------------------------------------------------
// fp32 -> (bf16 hi, bf16 lo), same layout, vectorized by 4
// ---------------------------------------------------------------------------
__global__ __launch_bounds__(256)
void split_act_kernel(const float* __restrict__ in,
                      __nv_bfloat16* __restrict__ hi, __nv_bfloat16* __restrict__ lo, int n4)
{
    int i = blockIdx.x * blockDim.x + threadIdx.x;
    if (i >= n4) return;
    float4 v = ((const float4*)in)[i];
    __nv_bfloat16 h0 = __float2bfloat16(v.x);
    __nv_bfloat16 h1 = __float2bfloat16(v.y);
    __nv_bfloat16 h2 = __float2bfloat16(v.z);
    __nv_bfloat16 h3 = __float2bfloat16(v.w);
    __nv_bfloat16 l0 = __float2bfloat16(v.x - __bfloat162float(h0));
    __nv_bfloat16 l1 = __float2bfloat16(v.y - __bfloat162float(h1));
    __nv_bfloat16 l2 = __float2bfloat16(v.z - __bfloat162float(h2));
    __nv_bfloat16 l3 = __float2bfloat16(v.w - __bfloat162float(h3));
    __nv_bfloat162* hp = (__nv_bfloat162*)hi;
    __nv_bfloat162* lp = (__nv_bfloat162*)lo;
    hp[2*i]   = __nv_bfloat162(h0, h1);
    hp[2*i+1] = __nv_bfloat162(h2, h3);
    lp[2*i]   = __nv_bfloat162(l0, l1);
    lp[2*i+1] = __nv_bfloat162(l2, l3);
}

// ---------------------------------------------------------------------------
// All 4 weights: fp32 W[K,N] -> bf16 hi/lo TRANSPOSED [N,K], one launch (z=4)
// ---------------------------------------------------------------------------
__global__ __launch_bounds__(256)
void split_w4_kernel(const float* __restrict__ W0, const float* __restrict__ W1,
                     const float* __restrict__ W2, const float* __restrict__ W3,
                     __nv_bfloat16* __restrict__ hi, __nv_bfloat16* __restrict__ lo)
{
    const float* W = (blockIdx.z == 0) ? W0 : (blockIdx.z == 1) ? W1
                   : (blockIdx.z == 2) ? W2 : W3;
    size_t dst_off = (size_t)blockIdx.z * DM_ * DM_;

    __shared__ float tile[32][33];
    int n0 = blockIdx.x * 32;
    int k0 = blockIdx.y * 32;
    int tx = threadIdx.x & 31;
    int ty = threadIdx.x >> 5;          // 0..7
#pragma unroll
    for (int i = 0; i < 32; i += 8)
        tile[ty + i][tx] = W[(size_t)(k0 + ty + i) * DM_ + n0 + tx];
    __syncthreads();
#pragma unroll
    for (int i = 0; i < 32; i += 8) {
        float x = tile[tx][ty + i];     // W[k0+tx][n0+ty+i]
        __nv_bfloat16 h = __float2bfloat16(x);
        __nv_bfloat16 l = __float2bfloat16(x - __bfloat162float(h));
        size_t o = dst_off + (size_t)(n0 + ty + i) * DM_ + k0 + tx;
        hi[o] = h;
        lo[o] = l;
    }
}

// ---------------------------------------------------------------------------
// bf16x3 HMMA GEMM: C[M,1024] = A[M,1024] @ B[N,K]^T
//  CTA tile 128x128, 8 warps (4x2), warp tile 32x64, BK=32, 3-stage cp.async.
//  2 CTAs/SM. SMEM row: 128B = [hi chunks 0..3 | lo chunks 0..3], XOR-8 swizzle.
//  MMA issue is TERM-MAJOR: all AhBh for the 8 accumulators, then AhBl, then
//  AlBh -> same-accumulator reuse distance 8 instructions (covers HMMA latency).
// ---------------------------------------------------------------------------
#define BKG 32
#define NSTG 3
#define STAGE_BYTES 32768            // A 16KB + B 16KB
#define GEMM_SMEM (NSTG * STAGE_BYTES + 128)
#define KSTAGES (DM_ / BKG)          // 32

__device__ __forceinline__ void load_stage_async(uint32_t sbase,
    const __nv_bfloat16* __restrict__ Ahi, const __nv_bfloat16* __restrict__ Alo,
    const __nv_bfloat16* __restrict__ Bhi, const __nv_bfloat16* __restrict__ Blo,
    int bm, int bn, int k0, int tid)
{
#pragma unroll
    for (int i = 0; i < 4; i++) {
        int idx = tid + i * 256;
        int r = idx >> 3, c = idx & 7;
        const __nv_bfloat16* src =
            (c < 4 ? Ahi : Alo) + (size_t)(bm + r) * DM_ + k0 + (c & 3) * 8;
        cp_async16(sbase + r * 128 + ((c ^ (r & 7)) * 16), src);
    }
#pragma unroll
    for (int i = 0; i < 4; i++) {
        int idx = tid + i * 256;
        int r = idx >> 3, c = idx & 7;
        const __nv_bfloat16* src =
            (c < 4 ? Bhi : Blo) + (size_t)(bn + r) * DM_ + k0 + (c & 3) * 8;
        cp_async16(sbase + 16384 + r * 128 + ((c ^ (r & 7)) * 16), src);
    }
}

__global__ __launch_bounds__(256, 2)
void gemm_bf16x3_mma_kernel(const __nv_bfloat16* __restrict__ Ahi,
                            const __nv_bfloat16* __restrict__ Alo,
                            const __nv_bfloat16* __restrict__ Bhi,
                            const __nv_bfloat16* __restrict__ Blo,
                            float* __restrict__ C)
{
    extern __shared__ char dsmem_raw[];
    uint32_t raw32 = smem_to_u32(dsmem_raw);
    uint32_t smem0 = (raw32 + 127u) & ~127u;

    const int tid = threadIdx.x;
    const int wid = tid >> 5;
    const int lane = tid & 31;
    const int warp_m = wid & 3;          // 4 warps in M
    const int warp_n = wid >> 2;         // 2 warps in N
    const int bm = blockIdx.y * 128;
    const int bn = blockIdx.x * 128;

    float acc[2][8][4];
#pragma unroll
    for (int mf = 0; mf < 2; mf++)
#pragma unroll
        for (int nf = 0; nf < 8; nf++)
#pragma unroll
            for (int q = 0; q < 4; q++) acc[mf][nf][q] = 0.f;

    // Prologue: stages 0 and 1 in flight
    load_stage_async(smem0, Ahi, Alo, Bhi, Blo, bm, bn, 0, tid);
    CP_ASYNC_COMMIT();
    load_stage_async(smem0 + STAGE_BYTES, Ahi, Alo, Bhi, Blo, bm, bn, BKG, tid);
    CP_ASYNC_COMMIT();

    const int a_row0 = warp_m * 32 + (lane & 15);
    const int b_row0 = warp_n * 64 + (lane & 15);
    const int khalf = lane >> 4;         // 0 or 1

    for (int s = 0; s < KSTAGES; s++) {
        CP_ASYNC_WAIT1();               // stage s resident
        __syncthreads();                // also: everyone finished iter s-1 reads
        if (s + 2 < KSTAGES) {
            load_stage_async(smem0 + ((s + 2) % NSTG) * STAGE_BYTES,
                             Ahi, Alo, Bhi, Blo, bm, bn, (s + 2) * BKG, tid);
        }
        CP_ASYNC_COMMIT();              // keep group count in lockstep

        uint32_t As = smem0 + (s % NSTG) * STAGE_BYTES;
        uint32_t Bs = As + 16384;

#pragma unroll
        for (int ks = 0; ks < 2; ks++) {
            uint32_t ah[2][4], al[2][4];
            const int ch = ks * 2 + khalf;           // hi chunk 0..3
#pragma unroll
            for (int mf = 0; mf < 2; mf++) {
                int row = a_row0 + mf * 16;
                ldmatrix_x4(ah[mf], As + row * 128 + ((ch ^ (row & 7)) * 16));
                ldmatrix_x4(al[mf], As + row * 128 + (((ch + 4) ^ (row & 7)) * 16));
            }
            // Process nf in two groups of 4 (bounds live registers for occ 2)
#pragma unroll
            for (int g = 0; g < 2; g++) {
                uint32_t bh[4][2], bl[4][2];
#pragma unroll
                for (int ng = 0; ng < 2; ng++) {
                    int row = b_row0 + (g * 2 + ng) * 16;
                    uint32_t t[4];
                    ldmatrix_x4(t, Bs + row * 128 + ((ch ^ (row & 7)) * 16));
                    bh[2*ng][0] = t[0]; bh[2*ng][1] = t[2];
                    bh[2*ng+1][0] = t[1]; bh[2*ng+1][1] = t[3];
                    ldmatrix_x4(t, Bs + row * 128 + (((ch + 4) ^ (row & 7)) * 16));
                    bl[2*ng][0] = t[0]; bl[2*ng][1] = t[2];
                    bl[2*ng+1][0] = t[1]; bl[2*ng+1][1] = t[3];
                }
                // TERM-MAJOR: 8-instruction reuse distance per accumulator
#pragma unroll
                for (int mf = 0; mf < 2; mf++)
#pragma unroll
                    for (int nf = 0; nf < 4; nf++)
                        mma_bf16(acc[mf][g * 4 + nf], ah[mf], bh[nf]);
#pragma unroll
                for (int mf = 0; mf < 2; mf++)
#pragma unroll
                    for (int nf = 0; nf < 4; nf++)
                        mma_bf16(acc[mf][g * 4 + nf], ah[mf], bl[nf]);
#pragma unroll
                for (int mf = 0; mf < 2; mf++)
#pragma unroll
                    for (int nf = 0; nf < 4; nf++)
                        mma_bf16(acc[mf][g * 4 + nf], al[mf], bh[nf]);
            }
        }
        // no trailing barrier: next iteration's leading sync covers the hazard
    }

    // Epilogue: write fp32 C
#pragma unroll
    for (int mf = 0; mf < 2; mf++) {
        int row = bm + warp_m * 32 + mf * 16 + (lane >> 2);
#pragma unroll
        for (int nf = 0; nf < 8; nf++) {
            int col = bn + warp_n * 64 + nf * 8 + (lane & 3) * 2;
            *(float2*)(C + (size_t)row * DM_ + col) =
                make_float2(acc[mf][nf][0], acc[mf][nf][1]);
            *(float2*)(C + (size_t)(row + 8) * DM_ + col) =
                make_float2(acc[mf][nf][2], acc[mf][nf][3]);
        }
    }
}

// ---------------------------------------------------------------------------
// Pass A (v2): warp per (b,h,c); lane = j*2+half. Each lane computes half of
// the 64-dim dot for band row j; 1 shuffle to combine halves; softmax over j
// via 4 xor-shuffles.
// ---------------------------------------------------------------------------
__global__ __launch_bounds__(256)
void attn_weights_kernel()
{
    int gw = blockIdx.x * 8 + (threadIdx.x >> 5);
    if (gw >= NB * H_ * LKV_) return;
    int lane = threadIdx.x & 31;

    int c = gw % LKV_;
    int h = (gw / LKV_) % H_;
    int b = gw / (LKV_ * H_);

    int j    = lane >> 1;       // 0..15 band row
    int half = lane & 1;        // which 32-dim half

    int nv = LQ_ - STRIDE_ * c;
    if (nv > SPAN_) nv = SPAN_;

    const float4* kp = (const float4*)(g_K + ((size_t)b * LKV_ + c) * DM_
                                       + h * DH_ + half * 32);
    float4 k4[8];
#pragma unroll
    for (int i = 0; i < 8; i++) k4[i] = kp[i];

    float d = 0.f;
    if (j < nv) {
        const float4* qp = (const float4*)(g_Q + ((size_t)b * LQ_ + STRIDE_ * c + j) * DM_
                                           + h * DH_ + half * 32);
#pragma unroll
        for (int i = 0; i < 8; i++) {
            float4 qv = qp[i];
            d += qv.x * k4[i].x + qv.y * k4[i].y + qv.z * k4[i].z + qv.w * k4[i].w;
        }
    }
    d += __shfl_xor_sync(0xffffffffu, d, 1);      // combine halves

    float dv = (j < nv) ? d : -CUDART_INF_F;
    float m = dv;
#pragma unroll
    for (int o = 2; o <= 16; o <<= 1) m = fmaxf(m, __shfl_xor_sync(0xffffffffu, m, o));
    float e = (j < nv) ? __expf(dv - m) : 0.f;
    float ssum = e;
#pragma unroll
    for (int o = 2; o <= 16; o <<= 1) ssum += __shfl_xor_sync(0xffffffffu, ssum, o);

    if (half == 0)
        g_W[(size_t)gw * SPAN_ + j] = e / ssum;
}

// ---------------------------------------------------------------------------
// Pass B: gather context rows; FUSED bf16 hi/lo split output (feeds Wo GEMM)
// ---------------------------------------------------------------------------
__global__ __launch_bounds__(1024)
void attn_ctx_kernel(__nv_bfloat16* __restrict__ chi, __nv_bfloat16* __restrict__ clo)
{
    int r = blockIdx.x % LQ_;
    int b = blockIdx.x / LQ_;
    int h = threadIdx.x >> 6;
    int d = threadIdx.x & 63;

    int c_hi = r >> 1;
    int c_lo = r - (SPAN_ - 1) <= 0 ? 0 : ((r - (SPAN_ - 1) + 1) >> 1);

    const float* vbase = g_V + (size_t)b * LKV_ * DM_ + h * DH_ + d;
    const float* wbase = g_W + (((size_t)b * H_ + h) * LKV_) * SPAN_;

    float acc = 0.f;
#pragma unroll
    for (int i = 0; i < (SPAN_ / STRIDE_); i++) {
        int c = c_hi - i;
        if (c < c_lo) break;
        int j = r - STRIDE_ * c;
        float w = wbase[(size_t)c * SPAN_ + j];
        acc += w * vbase[(size_t)c * DM_];
    }
    size_t o = ((size_t)b * LQ_ + r) * DM_ + h * DH_ + d;
    __nv_bfloat16 hi = __float2bfloat16(acc);
    __nv_bfloat16 lo = __float2bfloat16(acc - __bfloat162float(hi));
    chi[o] = hi;
    clo[o] = lo;
}

// ---------------------------------------------------------------------------
extern "C" void kernel_launch(void* const* d_in, const int* in_sizes, int n_in,
                              void* d_out, int out_size)
{
    const float* q  = (const float*)d_in[0];
    const float* k  = (const float*)d_in[1];
    const float* v  = (const float*)d_in[2];
    const float* Wq = (const float*)d_in[3];
    const float* Wk = (const float*)d_in[4];
    const float* Wv = (const float*)d_in[5];
    const float* Wo = (const float*)d_in[6];
    float* out = (float*)d_out;

    float *pQ, *pK, *pV;
    __nv_bfloat16 *pAhi, *pAlo, *pBhi, *pBlo;
    cudaGetSymbolAddress((void**)&pQ,   g_Q);
    cudaGetSymbolAddress((void**)&pK,   g_K);
    cudaGetSymbolAddress((void**)&pV,   g_V);
    cudaGetSymbolAddress((void**)&pAhi, g_Ahi);
    cudaGetSymbolAddress((void**)&pAlo, g_Alo);
    cudaGetSymbolAddress((void**)&pBhi, g_Bhi);
    cudaGetSymbolAddress((void**)&pBlo, g_Blo);

    cudaFuncSetAttribute(gemm_bf16x3_mma_kernel,
                         cudaFuncAttributeMaxDynamicSharedMemorySize, GEMM_SMEM);

    const size_t WSZ = (size_t)DM_ * DM_;

    // ---- All 4 weight splits in one launch (order: Wq, Wk, Wv, Wo)
    {
        dim3 grid(32, 32, 4);
        split_w4_kernel<<<grid, 256>>>(Wq, Wk, Wv, Wo, pBhi, pBlo);
    }
    // ---- Q projection: [8192,1024] @ Wq
    {
        int n4 = NB * LQ_ * DM_ / 4;
        split_act_kernel<<<n4 / 256, 256>>>(q, pAhi, pAlo, n4);
        dim3 grid(DM_ / 128, (NB * LQ_) / 128);
        gemm_bf16x3_mma_kernel<<<grid, 256, GEMM_SMEM>>>(pAhi, pAlo,
                                                         pBhi + 0 * WSZ, pBlo + 0 * WSZ, pQ);
    }
    // ---- K projection: [4096,1024] @ Wk
    {
        int n4 = NB * LKV_ * DM_ / 4;
        split_act_kernel<<<n4 / 256, 256>>>(k, pAhi, pAlo, n4);
        dim3 grid(DM_ / 128, (NB * LKV_) / 128);
        gemm_bf16x3_mma_kernel<<<grid, 256, GEMM_SMEM>>>(pAhi, pAlo,
                                                         pBhi + 1 * WSZ, pBlo + 1 * WSZ, pK);
    }
    // ---- V projection
    {
        int n4 = NB * LKV_ * DM_ / 4;
        split_act_kernel<<<n4 / 256, 256>>>(v, pAhi, pAlo, n4);
        dim3 grid(DM_ / 128, (NB * LKV_) / 128);
        gemm_bf16x3_mma_kernel<<<grid, 256, GEMM_SMEM>>>(pAhi, pAlo,
                                                         pBhi + 2 * WSZ, pBlo + 2 * WSZ, pV);
    }
    // ---- Attention (ctx kernel writes bf16 hi/lo directly into GEMM A bufs)
    {
        int total_warps = NB * H_ * LKV_;
        attn_weights_kernel<<<(total_warps + 7) / 8, 256>>>();
        attn_ctx_kernel<<<NB * LQ_, 1024>>>(pAhi, pAlo);
    }
    // ---- Output projection: ctx @ Wo -> out
    {
        dim3 grid(DM_ / 128, (NB * LQ_) / 128);
        gemm_bf16x3_mma_kernel<<<grid, 256, GEMM_SMEM>>>(pAhi, pAlo,
                                                         pBhi + 3 * WSZ, pBlo + 3 * WSZ, out);
    }
}